// round 1
// baseline (speedup 1.0000x reference)
#include <cuda_runtime.h>

// Problem dims (fixed by the reference setup_inputs)
#define B_DIM 8
#define T_DIM 2048
#define D_DIM 2048
#define M_DIM (B_DIM * T_DIM)   // 16384 rows

// Scratch for P' = (x @ Wp^T + bp) / 6   (128 MiB, allowed as __device__ global)
__device__ float g_P[(size_t)M_DIM * D_DIM];

// ---------------------------------------------------------------------------
// SGEMM: g_P[m][n] = (sum_k x[m][k] * Wp[n][k] + bp[n]) / 6
// A = x (M x K row-major), B = Wp (N x K row-major) -> P = A * B^T
// 128x128 block tile, BK=16, 8x8 per-thread microtile, 256 threads/CTA.
// M=16384, N=2048, K=2048 are all multiples of the tile dims: no bounds checks.
// ---------------------------------------------------------------------------
namespace gemm_cfg {
constexpr int BM = 128, BN = 128, BK = 16, TM = 8, TN = 8;
}

__global__ __launch_bounds__(256) void gemm_p_kernel(
    const float* __restrict__ A,   // x
    const float* __restrict__ W,   // Wp
    const float* __restrict__ bias // bp
) {
    using namespace gemm_cfg;
    const int K = D_DIM;

    __shared__ float As[BK][BM];
    __shared__ float Bs[BK][BN];

    const int tid  = threadIdx.x;
    const int brow = blockIdx.y * BM;
    const int bcol = blockIdx.x * BN;

    // compute-thread tile coordinates (16x16 thread grid of 8x8 microtiles)
    const int trow = (tid / 16) * TM;
    const int tcol = (tid % 16) * TN;

    // loader coordinates: 256 threads load a 128x16 tile as float4
    // each thread: 2 rows (lrow, lrow+64), 4 consecutive floats at lcol
    const int lrow = tid >> 2;        // 0..63
    const int lcol = (tid & 3) * 4;   // 0,4,8,12

    const float* Ab = A + (size_t)brow * K;
    const float* Wb = W + (size_t)bcol * K;

    float acc[TM][TN];
#pragma unroll
    for (int i = 0; i < TM; i++)
#pragma unroll
        for (int j = 0; j < TN; j++) acc[i][j] = 0.0f;

    for (int k0 = 0; k0 < K; k0 += BK) {
#pragma unroll
        for (int r = 0; r < 2; r++) {
            const int row = lrow + r * 64;
            const float4 av = *reinterpret_cast<const float4*>(
                Ab + (size_t)row * K + k0 + lcol);
            const float4 bv = *reinterpret_cast<const float4*>(
                Wb + (size_t)row * K + k0 + lcol);
            As[lcol + 0][row] = av.x;
            As[lcol + 1][row] = av.y;
            As[lcol + 2][row] = av.z;
            As[lcol + 3][row] = av.w;
            Bs[lcol + 0][row] = bv.x;
            Bs[lcol + 1][row] = bv.y;
            Bs[lcol + 2][row] = bv.z;
            Bs[lcol + 3][row] = bv.w;
        }
        __syncthreads();

#pragma unroll
        for (int kk = 0; kk < BK; kk++) {
            float ar[TM], br[TN];
#pragma unroll
            for (int i = 0; i < TM; i++) ar[i] = As[kk][trow + i];
#pragma unroll
            for (int j = 0; j < TN; j++) br[j] = Bs[kk][tcol + j];
#pragma unroll
            for (int i = 0; i < TM; i++)
#pragma unroll
                for (int j = 0; j < TN; j++)
                    acc[i][j] = fmaf(ar[i], br[j], acc[i][j]);
        }
        __syncthreads();
    }

    const float inv6 = 1.0f / 6.0f;
#pragma unroll
    for (int i = 0; i < TM; i++) {
        const size_t gr = (size_t)(brow + trow + i);
#pragma unroll
        for (int j = 0; j < TN; j += 4) {
            const int gc = bcol + tcol + j;
            float4 o;
            o.x = (acc[i][j + 0] + bias[gc + 0]) * inv6;
            o.y = (acc[i][j + 1] + bias[gc + 1]) * inv6;
            o.z = (acc[i][j + 2] + bias[gc + 2]) * inv6;
            o.w = (acc[i][j + 3] + bias[gc + 3]) * inv6;
            *reinterpret_cast<float4*>(&g_P[gr * D_DIM + gc]) = o;
        }
    }
}

// ---------------------------------------------------------------------------
// Fused chained-LayerNorm kernel. One CTA (256 threads) per (b, t) row.
//   t == 0      : out = LN(x[0]   + P'[1])
//   t == T-1    : out = LN(x[T-1] + P'[T-2])
//   otherwise   : out = LN( LN(x[t] + P'[t-1]) + P'[t+1] )
// ---------------------------------------------------------------------------
__device__ __forceinline__ float2 block_sum2(float a, float b) {
    __shared__ float sm[16];
    const int lane = threadIdx.x & 31;
    const int wid  = threadIdx.x >> 5;
#pragma unroll
    for (int o = 16; o > 0; o >>= 1) {
        a += __shfl_xor_sync(0xffffffffu, a, o);
        b += __shfl_xor_sync(0xffffffffu, b, o);
    }
    __syncthreads();  // protect sm against previous call's readers
    if (lane == 0) { sm[wid] = a; sm[8 + wid] = b; }
    __syncthreads();
    float sa = 0.0f, sb = 0.0f;
#pragma unroll
    for (int i = 0; i < 8; i++) { sa += sm[i]; sb += sm[8 + i]; }
    return make_float2(sa, sb);
}

__global__ __launch_bounds__(256) void ln_fuse_kernel(
    const float* __restrict__ x,
    const float* __restrict__ gamma,
    const float* __restrict__ beta,
    float* __restrict__ out
) {
    const int r   = blockIdx.x;          // global row, 0..M_DIM-1
    const int t   = r & (T_DIM - 1);     // T_DIM is a power of two
    const int tid = threadIdx.x;
    const float invD = 1.0f / (float)D_DIM;

    const float* xr  = x + (size_t)r * D_DIM;
    const int p1row  = (t == 0) ? (r + 1) : (r - 1);
    const float* pr1 = g_P + (size_t)p1row * D_DIM;

    float v[8];
    float s = 0.0f, sq = 0.0f;
#pragma unroll
    for (int i = 0; i < 8; i++) {
        const int j = i * 256 + tid;
        const float val = xr[j] + pr1[j];
        v[i] = val;
        s += val;
        sq += val * val;
    }
    float2 red = block_sum2(s, sq);
    float mean = red.x * invD;
    float var  = red.y * invD - mean * mean;
    float rstd = rsqrtf(var + 1e-5f);

    if (t >= 1 && t <= T_DIM - 2) {
        const float* pr2 = g_P + (size_t)(r + 1) * D_DIM;
        s = 0.0f; sq = 0.0f;
#pragma unroll
        for (int i = 0; i < 8; i++) {
            const int j = i * 256 + tid;
            const float inner = (v[i] - mean) * rstd * gamma[j] + beta[j];
            const float val = inner + pr2[j];
            v[i] = val;
            s += val;
            sq += val * val;
        }
        red  = block_sum2(s, sq);
        mean = red.x * invD;
        var  = red.y * invD - mean * mean;
        rstd = rsqrtf(var + 1e-5f);
    }

    float* orow = out + (size_t)r * D_DIM;
#pragma unroll
    for (int i = 0; i < 8; i++) {
        const int j = i * 256 + tid;
        orow[j] = (v[i] - mean) * rstd * gamma[j] + beta[j];
    }
}

// ---------------------------------------------------------------------------
// Launch. Input order per metadata: x, W1, b1, W2, b2, Wp, bp, gamma, beta.
// The W1/b1/W2/b2 branch is provably dead: scale = mean(softmax(.)) = 1/6.
// ---------------------------------------------------------------------------
extern "C" void kernel_launch(void* const* d_in, const int* in_sizes, int n_in,
                              void* d_out, int out_size) {
    const float* x     = (const float*)d_in[0];
    const float* Wp    = (const float*)d_in[5];
    const float* bp    = (const float*)d_in[6];
    const float* gamma = (const float*)d_in[7];
    const float* beta  = (const float*)d_in[8];
    float* out = (float*)d_out;

    dim3 ggrid(D_DIM / gemm_cfg::BN, M_DIM / gemm_cfg::BM);
    gemm_p_kernel<<<ggrid, 256>>>(x, Wp, bp);
    ln_fuse_kernel<<<M_DIM, 256>>>(x, gamma, beta, out);
}

// round 3
// speedup vs baseline: 6.9239x; 6.9239x over previous
#include <cuda_runtime.h>
#include <cuda_fp16.h>
#include <cstdint>

#define B_DIM 8
#define T_DIM 2048
#define D_DIM 2048
#define M_DIM (B_DIM * T_DIM)   // 16384

// ---------------- device-global scratch (static, allowed) -------------------
__device__ __align__(256) float  g_P[(size_t)M_DIM * D_DIM];  // P' = (x@Wp^T+bp)/6
__device__ __align__(256) __half g_A[(size_t)M_DIM * D_DIM];  // fp16(x)
__device__ __align__(256) __half g_B[(size_t)D_DIM * D_DIM];  // fp16(Wp)

// ---------------- helpers ----------------------------------------------------
__device__ __forceinline__ uint32_t smem_u32(const void* p) {
    uint32_t a;
    asm("{ .reg .u64 t; cvta.to.shared.u64 t, %1; cvt.u32.u64 %0, t; }" : "=r"(a) : "l"(p));
    return a;
}
__device__ __forceinline__ void cp16(uint32_t sdst, const void* gsrc) {
    asm volatile("cp.async.cg.shared.global [%0], [%1], 16;" :: "r"(sdst), "l"(gsrc));
}
__device__ __forceinline__ uint32_t sw128(uint32_t o) {   // SW128 swizzle
    return o ^ ((o >> 3) & 0x70);
}
__device__ __forceinline__ void ldmatrix_x4(uint32_t* f, uint32_t addr) {
    asm volatile("ldmatrix.sync.aligned.m8n8.x4.shared.b16 {%0,%1,%2,%3}, [%4];"
                 : "=r"(f[0]), "=r"(f[1]), "=r"(f[2]), "=r"(f[3]) : "r"(addr));
}
__device__ __forceinline__ void mma16816(float* c, const uint32_t* a,
                                         uint32_t b0, uint32_t b1) {
    asm volatile(
        "mma.sync.aligned.m16n8k16.row.col.f32.f16.f16.f32 "
        "{%0,%1,%2,%3}, {%4,%5,%6,%7}, {%8,%9}, {%0,%1,%2,%3};"
        : "+f"(c[0]), "+f"(c[1]), "+f"(c[2]), "+f"(c[3])
        : "r"(a[0]), "r"(a[1]), "r"(a[2]), "r"(a[3]), "r"(b0), "r"(b1));
}

// ---------------- fp32 -> fp16 convert ---------------------------------------
__global__ __launch_bounds__(256) void cvt_fp16_kernel(
    const float4* __restrict__ src, uint2* __restrict__ dst, int n4) {
    int i = blockIdx.x * 256 + threadIdx.x;
    if (i >= n4) return;
    float4 v = src[i];
    __half2 h0 = __floats2half2_rn(v.x, v.y);
    __half2 h1 = __floats2half2_rn(v.z, v.w);
    dst[i] = make_uint2(*reinterpret_cast<uint32_t*>(&h0),
                        *reinterpret_cast<uint32_t*>(&h1));
}

// ---------------- HMMA GEMM: g_P = (A @ B^T + bp) / 6 ------------------------
// A: M x K fp16 row-major, B: N x K fp16 row-major. M=16384, N=K=2048.
// BM=128, BN=128, BK=64, 256 threads (8 warps, 4x2), 3-stage cp.async pipeline.
namespace hg {
constexpr int BM = 128, BN = 128, BK = 64, STAGES = 3;
constexpr int NKT = D_DIM / BK;                 // 32
constexpr int TILE_BYTES = BM * 128;            // 16 KB (128 B per row, SW128)
constexpr int SMEM_BYTES = 2 * STAGES * TILE_BYTES + 1024;  // + align pad
}

__global__ __launch_bounds__(256, 2) void gemm_hmma_kernel(const float* __restrict__ bias) {
    using namespace hg;
    extern __shared__ char smem_raw[];
    const uint32_t sbase = (smem_u32(smem_raw) + 1023u) & ~1023u;

    const int tid  = threadIdx.x;
    const int wid  = tid >> 5;
    const int lane = tid & 31;
    const int brow = blockIdx.y * BM;
    const int bcol = blockIdx.x * BN;
    const int wm = wid & 3;      // 4 warps in M -> 32 rows each
    const int wn = wid >> 2;     // 2 warps in N -> 64 cols each

    const __half* Ag = g_A + (size_t)brow * D_DIM;
    const __half* Bg = g_B + (size_t)bcol * D_DIM;

    // loader: 128 rows x 8 segs(16B) per tile, 4 passes of 256 threads
    const int lrow = tid >> 3;          // base row 0..31 step handled by pass
    const int lseg = tid & 7;

    auto load_stage = [&](int s, int k0) {
        const uint32_t a_s = sbase + s * TILE_BYTES;
        const uint32_t b_s = sbase + (STAGES + s) * TILE_BYTES;
#pragma unroll
        for (int p = 0; p < 4; p++) {
            const int row = lrow + p * 32;
            const uint32_t off = sw128((uint32_t)(row * 128 + lseg * 16));
            const size_t gofs = (size_t)row * D_DIM + k0 + lseg * 8;
            cp16(a_s + off, Ag + gofs);
            cp16(b_s + off, Bg + gofs);
        }
    };

    float acc[2][8][4];
#pragma unroll
    for (int i = 0; i < 2; i++)
#pragma unroll
        for (int j = 0; j < 8; j++)
#pragma unroll
            for (int e = 0; e < 4; e++) acc[i][j][e] = 0.0f;

    // prologue: stages 0..STAGES-2
#pragma unroll
    for (int s = 0; s < STAGES - 1; s++) {
        load_stage(s, s * BK);
        asm volatile("cp.async.commit_group;" ::: "memory");
    }

    // fragment address components (constant per thread across ksteps)
    const int a_r_base = wm * 32 + (lane & 15);
    const int ab_cb    = ((lane >> 4) << 4);   // 0 or 16
    const int b_r_base = wn * 64 + (lane & 7) + ((lane >> 3) & 1) * 8;

#pragma unroll 1
    for (int kt = 0; kt < NKT; kt++) {
        asm volatile("cp.async.wait_group 1;" ::: "memory");
        __syncthreads();

        const int pf = kt + STAGES - 1;
        if (pf < NKT) load_stage(pf % STAGES, pf * BK);
        asm volatile("cp.async.commit_group;" ::: "memory");

        const int s = kt % STAGES;
        const uint32_t a_s = sbase + s * TILE_BYTES;
        const uint32_t b_s = sbase + (STAGES + s) * TILE_BYTES;

#pragma unroll
        for (int kk = 0; kk < BK / 16; kk++) {
            const int kb = kk * 32;   // bytes (16 halves)
            uint32_t af[2][4];
#pragma unroll
            for (int i = 0; i < 2; i++) {
                const int r = a_r_base + i * 16;
                ldmatrix_x4(af[i], a_s + sw128((uint32_t)(r * 128 + kb + ab_cb)));
            }
            uint32_t bf[4][4];
#pragma unroll
            for (int j = 0; j < 4; j++) {
                const int r = b_r_base + j * 16;
                ldmatrix_x4(bf[j], b_s + sw128((uint32_t)(r * 128 + kb + ab_cb)));
            }
#pragma unroll
            for (int i = 0; i < 2; i++)
#pragma unroll
                for (int j = 0; j < 4; j++) {
                    mma16816(acc[i][2 * j],     af[i], bf[j][0], bf[j][2]);
                    mma16816(acc[i][2 * j + 1], af[i], bf[j][1], bf[j][3]);
                }
        }
    }

    // epilogue: c frag lane mapping: rows l/4 (+8), cols (l%4)*2 (+1)
    const float inv6 = 1.0f / 6.0f;
    const int prow0 = brow + wm * 32 + (lane >> 2);
    const int pcol0 = bcol + wn * 64 + (lane & 3) * 2;
#pragma unroll
    for (int i = 0; i < 2; i++) {
        const size_t r0 = (size_t)(prow0 + i * 16);
#pragma unroll
        for (int j = 0; j < 8; j++) {
            const int c = pcol0 + j * 8;
            const float b0 = bias[c], b1 = bias[c + 1];
            float2 lo, hi;
            lo.x = (acc[i][j][0] + b0) * inv6;
            lo.y = (acc[i][j][1] + b1) * inv6;
            hi.x = (acc[i][j][2] + b0) * inv6;
            hi.y = (acc[i][j][3] + b1) * inv6;
            *reinterpret_cast<float2*>(&g_P[r0 * D_DIM + c])       = lo;
            *reinterpret_cast<float2*>(&g_P[(r0 + 8) * D_DIM + c]) = hi;
        }
    }
}

// ---------------- fused chained LayerNorm (near roofline from R1) ------------
__device__ __forceinline__ float2 block_sum2(float a, float b) {
    __shared__ float sm[16];
    const int lane = threadIdx.x & 31;
    const int wid  = threadIdx.x >> 5;
#pragma unroll
    for (int o = 16; o > 0; o >>= 1) {
        a += __shfl_xor_sync(0xffffffffu, a, o);
        b += __shfl_xor_sync(0xffffffffu, b, o);
    }
    __syncthreads();
    if (lane == 0) { sm[wid] = a; sm[8 + wid] = b; }
    __syncthreads();
    float sa = 0.0f, sb = 0.0f;
#pragma unroll
    for (int i = 0; i < 8; i++) { sa += sm[i]; sb += sm[8 + i]; }
    return make_float2(sa, sb);
}

__global__ __launch_bounds__(256) void ln_fuse_kernel(
    const float* __restrict__ x, const float* __restrict__ gamma,
    const float* __restrict__ beta, float* __restrict__ out) {
    const int r   = blockIdx.x;
    const int t   = r & (T_DIM - 1);
    const int tid = threadIdx.x;
    const float invD = 1.0f / (float)D_DIM;

    const float* xr  = x + (size_t)r * D_DIM;
    const int p1row  = (t == 0) ? (r + 1) : (r - 1);
    const float* pr1 = g_P + (size_t)p1row * D_DIM;

    float v[8];
    float s = 0.0f, sq = 0.0f;
#pragma unroll
    for (int i = 0; i < 8; i++) {
        const int j = i * 256 + tid;
        const float val = xr[j] + pr1[j];
        v[i] = val; s += val; sq += val * val;
    }
    float2 red = block_sum2(s, sq);
    float mean = red.x * invD;
    float var  = red.y * invD - mean * mean;
    float rstd = rsqrtf(var + 1e-5f);

    if (t >= 1 && t <= T_DIM - 2) {
        const float* pr2 = g_P + (size_t)(r + 1) * D_DIM;
        s = 0.0f; sq = 0.0f;
#pragma unroll
        for (int i = 0; i < 8; i++) {
            const int j = i * 256 + tid;
            const float inner = (v[i] - mean) * rstd * gamma[j] + beta[j];
            const float val = inner + pr2[j];
            v[i] = val; s += val; sq += val * val;
        }
        red  = block_sum2(s, sq);
        mean = red.x * invD;
        var  = red.y * invD - mean * mean;
        rstd = rsqrtf(var + 1e-5f);
    }

    float* orow = out + (size_t)r * D_DIM;
#pragma unroll
    for (int i = 0; i < 8; i++) {
        const int j = i * 256 + tid;
        orow[j] = (v[i] - mean) * rstd * gamma[j] + beta[j];
    }
}

// ---------------- launch ------------------------------------------------------
extern "C" void kernel_launch(void* const* d_in, const int* in_sizes, int n_in,
                              void* d_out, int out_size) {
    const float* x     = (const float*)d_in[0];
    const float* Wp    = (const float*)d_in[5];
    const float* bp    = (const float*)d_in[6];
    const float* gamma = (const float*)d_in[7];
    const float* beta  = (const float*)d_in[8];
    float* out = (float*)d_out;

    static bool attr_set = false;
    if (!attr_set) {
        cudaFuncSetAttribute(gemm_hmma_kernel,
                             cudaFuncAttributeMaxDynamicSharedMemorySize, hg::SMEM_BYTES);
        attr_set = true;
    }

    __half* gA; cudaGetSymbolAddress((void**)&gA, g_A);
    __half* gB; cudaGetSymbolAddress((void**)&gB, g_B);

    const int nx4 = M_DIM * D_DIM / 4;
    const int nw4 = D_DIM * D_DIM / 4;
    cvt_fp16_kernel<<<nx4 / 256, 256>>>((const float4*)x,  (uint2*)gA, nx4);
    cvt_fp16_kernel<<<nw4 / 256, 256>>>((const float4*)Wp, (uint2*)gB, nw4);

    dim3 ggrid(D_DIM / hg::BN, M_DIM / hg::BM);   // (16, 128)
    gemm_hmma_kernel<<<ggrid, 256, hg::SMEM_BYTES>>>(bp);

    ln_fuse_kernel<<<M_DIM, 256>>>(x, gamma, beta, out);
}

// round 4
// speedup vs baseline: 6.9393x; 1.0022x over previous
#include <cuda_runtime.h>
#include <cuda_fp16.h>
#include <cstdint>

#define B_DIM 8
#define T_DIM 2048
#define D_DIM 2048
#define M_DIM (B_DIM * T_DIM)   // 16384

// ---------------- device-global scratch (static, allowed) -------------------
__device__ __align__(256) float  g_P[(size_t)M_DIM * D_DIM];  // P' = (x@Wp^T+bp)/6
__device__ __align__(256) __half g_A[(size_t)M_DIM * D_DIM];  // fp16(x)
__device__ __align__(256) __half g_B[(size_t)D_DIM * D_DIM];  // fp16(Wp)

// ---------------- helpers ----------------------------------------------------
__device__ __forceinline__ uint32_t smem_u32(const void* p) {
    uint32_t a;
    asm("{ .reg .u64 t; cvta.to.shared.u64 t, %1; cvt.u32.u64 %0, t; }" : "=r"(a) : "l"(p));
    return a;
}
__device__ __forceinline__ void cp16(uint32_t sdst, const void* gsrc) {
    asm volatile("cp.async.cg.shared.global [%0], [%1], 16;" :: "r"(sdst), "l"(gsrc));
}
__device__ __forceinline__ uint32_t sw128(uint32_t o) {   // SW128 swizzle
    return o ^ ((o >> 3) & 0x70);
}
__device__ __forceinline__ void ldmatrix_x4(uint32_t* f, uint32_t addr) {
    asm volatile("ldmatrix.sync.aligned.m8n8.x4.shared.b16 {%0,%1,%2,%3}, [%4];"
                 : "=r"(f[0]), "=r"(f[1]), "=r"(f[2]), "=r"(f[3]) : "r"(addr));
}
__device__ __forceinline__ void mma16816(float* c, const uint32_t* a,
                                         uint32_t b0, uint32_t b1) {
    asm volatile(
        "mma.sync.aligned.m16n8k16.row.col.f32.f16.f16.f32 "
        "{%0,%1,%2,%3}, {%4,%5,%6,%7}, {%8,%9}, {%0,%1,%2,%3};"
        : "+f"(c[0]), "+f"(c[1]), "+f"(c[2]), "+f"(c[3])
        : "r"(a[0]), "r"(a[1]), "r"(a[2]), "r"(a[3]), "r"(b0), "r"(b1));
}

// ---------------- fp32 -> fp16 convert ---------------------------------------
__global__ __launch_bounds__(256) void cvt_fp16_kernel(
    const float4* __restrict__ src, uint2* __restrict__ dst, int n4) {
    int i = blockIdx.x * 256 + threadIdx.x;
    if (i >= n4) return;
    float4 v = src[i];
    __half2 h0 = __floats2half2_rn(v.x, v.y);
    __half2 h1 = __floats2half2_rn(v.z, v.w);
    dst[i] = make_uint2(*reinterpret_cast<uint32_t*>(&h0),
                        *reinterpret_cast<uint32_t*>(&h1));
}

// ---------------- HMMA GEMM: g_P = (A @ B^T + bp) / 6 ------------------------
// A: M x K fp16 row-major, B: N x K fp16 row-major. M=16384, N=K=2048.
// BM=128, BN=128, BK=64, 256 threads (8 warps, 4x2), 3-stage cp.async pipeline.
namespace hg {
constexpr int BM = 128, BN = 128, BK = 64, STAGES = 3;
constexpr int NKT = D_DIM / BK;                 // 32
constexpr int TILE_BYTES = BM * 128;            // 16 KB (128 B per row, SW128)
constexpr int SMEM_BYTES = 2 * STAGES * TILE_BYTES + 1024;  // + align pad
}

__global__ __launch_bounds__(256, 2) void gemm_hmma_kernel(const float* __restrict__ bias) {
    using namespace hg;
    extern __shared__ char smem_raw[];
    const uint32_t sbase = (smem_u32(smem_raw) + 1023u) & ~1023u;

    const int tid  = threadIdx.x;
    const int wid  = tid >> 5;
    const int lane = tid & 31;
    const int brow = blockIdx.y * BM;
    const int bcol = blockIdx.x * BN;
    const int wm = wid & 3;      // 4 warps in M -> 32 rows each
    const int wn = wid >> 2;     // 2 warps in N -> 64 cols each

    const __half* Ag = g_A + (size_t)brow * D_DIM;
    const __half* Bg = g_B + (size_t)bcol * D_DIM;

    // loader: 128 rows x 8 segs(16B) per tile, 4 passes of 256 threads
    const int lrow = tid >> 3;          // base row 0..31 step handled by pass
    const int lseg = tid & 7;

    auto load_stage = [&](int s, int k0) {
        const uint32_t a_s = sbase + s * TILE_BYTES;
        const uint32_t b_s = sbase + (STAGES + s) * TILE_BYTES;
#pragma unroll
        for (int p = 0; p < 4; p++) {
            const int row = lrow + p * 32;
            const uint32_t off = sw128((uint32_t)(row * 128 + lseg * 16));
            const size_t gofs = (size_t)row * D_DIM + k0 + lseg * 8;
            cp16(a_s + off, Ag + gofs);
            cp16(b_s + off, Bg + gofs);
        }
    };

    float acc[2][8][4];
#pragma unroll
    for (int i = 0; i < 2; i++)
#pragma unroll
        for (int j = 0; j < 8; j++)
#pragma unroll
            for (int e = 0; e < 4; e++) acc[i][j][e] = 0.0f;

    // prologue: stages 0..STAGES-2
#pragma unroll
    for (int s = 0; s < STAGES - 1; s++) {
        load_stage(s, s * BK);
        asm volatile("cp.async.commit_group;" ::: "memory");
    }

    // fragment address components (constant per thread across ksteps)
    const int a_r_base = wm * 32 + (lane & 15);
    const int ab_cb    = ((lane >> 4) << 4);   // 0 or 16
    const int b_r_base = wn * 64 + (lane & 7) + ((lane >> 3) & 1) * 8;

#pragma unroll 1
    for (int kt = 0; kt < NKT; kt++) {
        asm volatile("cp.async.wait_group 1;" ::: "memory");
        __syncthreads();

        const int pf = kt + STAGES - 1;
        if (pf < NKT) load_stage(pf % STAGES, pf * BK);
        asm volatile("cp.async.commit_group;" ::: "memory");

        const int s = kt % STAGES;
        const uint32_t a_s = sbase + s * TILE_BYTES;
        const uint32_t b_s = sbase + (STAGES + s) * TILE_BYTES;

#pragma unroll
        for (int kk = 0; kk < BK / 16; kk++) {
            const int kb = kk * 32;   // bytes (16 halves)
            uint32_t af[2][4];
#pragma unroll
            for (int i = 0; i < 2; i++) {
                const int r = a_r_base + i * 16;
                ldmatrix_x4(af[i], a_s + sw128((uint32_t)(r * 128 + kb + ab_cb)));
            }
            uint32_t bf[4][4];
#pragma unroll
            for (int j = 0; j < 4; j++) {
                const int r = b_r_base + j * 16;
                ldmatrix_x4(bf[j], b_s + sw128((uint32_t)(r * 128 + kb + ab_cb)));
            }
#pragma unroll
            for (int i = 0; i < 2; i++)
#pragma unroll
                for (int j = 0; j < 4; j++) {
                    mma16816(acc[i][2 * j],     af[i], bf[j][0], bf[j][2]);
                    mma16816(acc[i][2 * j + 1], af[i], bf[j][1], bf[j][3]);
                }
        }
    }

    // epilogue: c frag lane mapping: rows l/4 (+8), cols (l%4)*2 (+1)
    const float inv6 = 1.0f / 6.0f;
    const int prow0 = brow + wm * 32 + (lane >> 2);
    const int pcol0 = bcol + wn * 64 + (lane & 3) * 2;
#pragma unroll
    for (int i = 0; i < 2; i++) {
        const size_t r0 = (size_t)(prow0 + i * 16);
#pragma unroll
        for (int j = 0; j < 8; j++) {
            const int c = pcol0 + j * 8;
            const float b0 = bias[c], b1 = bias[c + 1];
            float2 lo, hi;
            lo.x = (acc[i][j][0] + b0) * inv6;
            lo.y = (acc[i][j][1] + b1) * inv6;
            hi.x = (acc[i][j][2] + b0) * inv6;
            hi.y = (acc[i][j][3] + b1) * inv6;
            *reinterpret_cast<float2*>(&g_P[r0 * D_DIM + c])       = lo;
            *reinterpret_cast<float2*>(&g_P[(r0 + 8) * D_DIM + c]) = hi;
        }
    }
}

// ---------------- fused chained LayerNorm (near roofline from R1) ------------
__device__ __forceinline__ float2 block_sum2(float a, float b) {
    __shared__ float sm[16];
    const int lane = threadIdx.x & 31;
    const int wid  = threadIdx.x >> 5;
#pragma unroll
    for (int o = 16; o > 0; o >>= 1) {
        a += __shfl_xor_sync(0xffffffffu, a, o);
        b += __shfl_xor_sync(0xffffffffu, b, o);
    }
    __syncthreads();
    if (lane == 0) { sm[wid] = a; sm[8 + wid] = b; }
    __syncthreads();
    float sa = 0.0f, sb = 0.0f;
#pragma unroll
    for (int i = 0; i < 8; i++) { sa += sm[i]; sb += sm[8 + i]; }
    return make_float2(sa, sb);
}

__global__ __launch_bounds__(256) void ln_fuse_kernel(
    const float* __restrict__ x, const float* __restrict__ gamma,
    const float* __restrict__ beta, float* __restrict__ out) {
    const int r   = blockIdx.x;
    const int t   = r & (T_DIM - 1);
    const int tid = threadIdx.x;
    const float invD = 1.0f / (float)D_DIM;

    const float* xr  = x + (size_t)r * D_DIM;
    const int p1row  = (t == 0) ? (r + 1) : (r - 1);
    const float* pr1 = g_P + (size_t)p1row * D_DIM;

    float v[8];
    float s = 0.0f, sq = 0.0f;
#pragma unroll
    for (int i = 0; i < 8; i++) {
        const int j = i * 256 + tid;
        const float val = xr[j] + pr1[j];
        v[i] = val; s += val; sq += val * val;
    }
    float2 red = block_sum2(s, sq);
    float mean = red.x * invD;
    float var  = red.y * invD - mean * mean;
    float rstd = rsqrtf(var + 1e-5f);

    if (t >= 1 && t <= T_DIM - 2) {
        const float* pr2 = g_P + (size_t)(r + 1) * D_DIM;
        s = 0.0f; sq = 0.0f;
#pragma unroll
        for (int i = 0; i < 8; i++) {
            const int j = i * 256 + tid;
            const float inner = (v[i] - mean) * rstd * gamma[j] + beta[j];
            const float val = inner + pr2[j];
            v[i] = val; s += val; sq += val * val;
        }
        red  = block_sum2(s, sq);
        mean = red.x * invD;
        var  = red.y * invD - mean * mean;
        rstd = rsqrtf(var + 1e-5f);
    }

    float* orow = out + (size_t)r * D_DIM;
#pragma unroll
    for (int i = 0; i < 8; i++) {
        const int j = i * 256 + tid;
        orow[j] = (v[i] - mean) * rstd * gamma[j] + beta[j];
    }
}

// ---------------- launch ------------------------------------------------------
extern "C" void kernel_launch(void* const* d_in, const int* in_sizes, int n_in,
                              void* d_out, int out_size) {
    const float* x     = (const float*)d_in[0];
    const float* Wp    = (const float*)d_in[5];
    const float* bp    = (const float*)d_in[6];
    const float* gamma = (const float*)d_in[7];
    const float* beta  = (const float*)d_in[8];
    float* out = (float*)d_out;

    static bool attr_set = false;
    if (!attr_set) {
        cudaFuncSetAttribute(gemm_hmma_kernel,
                             cudaFuncAttributeMaxDynamicSharedMemorySize, hg::SMEM_BYTES);
        attr_set = true;
    }

    __half* gA; cudaGetSymbolAddress((void**)&gA, g_A);
    __half* gB; cudaGetSymbolAddress((void**)&gB, g_B);

    const int nx4 = M_DIM * D_DIM / 4;
    const int nw4 = D_DIM * D_DIM / 4;
    cvt_fp16_kernel<<<nx4 / 256, 256>>>((const float4*)x,  (uint2*)gA, nx4);
    cvt_fp16_kernel<<<nw4 / 256, 256>>>((const float4*)Wp, (uint2*)gB, nw4);

    dim3 ggrid(D_DIM / hg::BN, M_DIM / hg::BM);   // (16, 128)
    gemm_hmma_kernel<<<ggrid, 256, hg::SMEM_BYTES>>>(bp);

    ln_fuse_kernel<<<M_DIM, 256>>>(x, gamma, beta, out);
}